// round 14
// baseline (speedup 1.0000x reference)
#include <cuda_runtime.h>
#include <cuda_bf16.h>
#include <math.h>

#define NN 32768
#define EE 262144
#define FF 64
#define ZZ 10
#define NBB 8
#define LL 2
#define HH 16
#define NPAD (NN + 64 * ZZ)              /* species-padded node ordering */
#define EPS_SC 0.24253562503633297f      /* 1/sqrt(17) */

typedef unsigned long long u64;

// ---------------- packed fp32x2 helpers ----------------------------------------
__device__ __forceinline__ u64 pack2(float lo, float hi) {
    u64 r; asm("mov.b64 %0, {%1, %2};" : "=l"(r) : "f"(lo), "f"(hi)); return r;
}
__device__ __forceinline__ u64 bcast2(float v) { return pack2(v, v); }
__device__ __forceinline__ float2 u2f(u64 v) {
    float2 r; asm("mov.b64 {%0, %1}, %2;" : "=f"(r.x), "=f"(r.y) : "l"(v)); return r;
}
__device__ __forceinline__ u64 fma2(u64 a, u64 b, u64 c) {
    u64 r; asm("fma.rn.f32x2 %0, %1, %2, %3;" : "=l"(r) : "l"(a), "l"(b), "l"(c)); return r;
}
__device__ __forceinline__ u64 mul2(u64 a, u64 b) {
    u64 r; asm("mul.rn.f32x2 %0, %1, %2;" : "=l"(r) : "l"(a), "l"(b)); return r;
}
__device__ __forceinline__ float hsum2(u64 v) {
    float2 f = u2f(v); return f.x + f.y;
}
#define BAR_SLOT(id) asm volatile("bar.sync %0, 64;" :: "r"(id) : "memory")

// ---------------- scratch (static device globals; no allocation) -------------
// Combined node state: per (node, f-pair t) one 32B record
//   (s[2t], s[2t+1], vx[2t], vx[2t+1], vy[2t], vy[2t+1], vz[2t], vz[2t+1])
__device__ float  g_sv[(size_t)NN * 32 * 8];
__device__ float4 g_rbf4s[EE * 2];       // bessel basis, receiver-sorted
__device__ float4 g_Y4s[EE];             // unit vector, receiver-sorted
__device__ int    g_snds[EE];            // sender | (sender_species << 20), sorted
__device__ int    g_cnt[NN];             // receiver histogram
__device__ int    g_cur[NN];             // scatter cursors
__device__ int    g_off[NN + 1];         // CSR offsets
__device__ int    g_scnt[ZZ];            // species histogram
__device__ int    g_scur[ZZ];
__device__ int    g_norder[NPAD];        // species-grouped node order (-1 pad)

// ---------------- preprocessing ------------------------------------------------
__global__ void zero_sort_kernel()
{
    int i = blockIdx.x * blockDim.x + threadIdx.x;
    if (i < NN)   g_cnt[i] = 0;
    if (i < ZZ)   g_scnt[i] = 0;
    if (i < NPAD) g_norder[i] = -1;
}

__global__ void hist_kernel(const int* __restrict__ receivers,
                            const int* __restrict__ species)
{
    int i = blockIdx.x * blockDim.x + threadIdx.x;
    if (i < EE) atomicAdd(&g_cnt[receivers[i]], 1);
    if (i < NN) atomicAdd(&g_scnt[species[i]], 1);
}

__global__ void scan_kernel()   // 1 block, 1024 threads; NN = 1024*32
{
    __shared__ int part[1024];
    int tid = threadIdx.x;

    if (tid == 0) {             // tiny species scan folded in
        int off = 0;
#pragma unroll
        for (int z = 0; z < ZZ; z++) {
            g_scur[z] = off;
            off += ((g_scnt[z] + 63) / 64) * 64;
        }
    }

    int base = tid * 32;
    int cnt[32];
#pragma unroll
    for (int j = 0; j < 8; j++)
        *(int4*)&cnt[j * 4] = *(const int4*)&g_cnt[base + j * 4];

    int loc[32];
    int sum = 0;
#pragma unroll
    for (int j = 0; j < 32; j++) { loc[j] = sum; sum += cnt[j]; }
    part[tid] = sum;
    __syncthreads();
    for (int o = 1; o < 1024; o <<= 1) {
        int v = (tid >= o) ? part[tid - o] : 0;
        __syncthreads();
        part[tid] += v;
        __syncthreads();
    }
    int pref = part[tid] - sum;
#pragma unroll
    for (int j = 0; j < 32; j++) {
        int o = pref + loc[j];
        g_off[base + j] = o;
        g_cur[base + j] = o;
    }
    if (tid == 1023) g_off[NN] = part[1023];
}

// precompute (edge scatter) + species scatter, one launch
__global__ void fused_pre_kernel(const float* __restrict__ vectors,
                                 const int* __restrict__ senders,
                                 const int* __restrict__ receivers,
                                 const int* __restrict__ species)
{
    int idx = blockIdx.x * blockDim.x + threadIdx.x;   // EE threads

    if (idx < EE) {
        float x = vectors[idx * 3 + 0];
        float y = vectors[idx * 3 + 1];
        float z = vectors[idx * 3 + 2];
        float r2 = x * x + y * y + z * z + 1e-12f;
        float r  = sqrtf(r2);
        float inv = 1.0f / r;
        float rc = fmaxf(r, 1e-6f);
        float r6 = r2 * r2 * r2;
        float env = 1.0f - 28.0f * r6 + 48.0f * r6 * r - 21.0f * r6 * r2;
        if (r >= 1.0f) env = 0.0f;
        float kk = env * 1.4142135623730951f / rc;
        float pr = 3.14159265358979323846f * rc;
        float rb[NBB];
#pragma unroll
        for (int n2 = 1; n2 <= NBB; n2++)
            rb[n2 - 1] = kk * __sinf((float)n2 * pr);

        int snd = senders[idx];
        int pos = atomicAdd(&g_cur[receivers[idx]], 1);
        g_Y4s[pos] = make_float4(x * inv, y * inv, z * inv, 0.f);
        g_rbf4s[pos * 2 + 0] = make_float4(rb[0], rb[1], rb[2], rb[3]);
        g_rbf4s[pos * 2 + 1] = make_float4(rb[4], rb[5], rb[6], rb[7]);
        g_snds[pos] = snd | (species[snd] << 20);
    }

    if (idx < NN) {
        int pos = atomicAdd(&g_scur[species[idx]], 1);
        g_norder[pos] = idx;
    }
}

// ---------------- layer 0 kernel (warp-per-node, R12 structure) -----------------
#define SMEM_L0 ((16384 + 1024 + 8 * 256) * 4)   /* 76 KB */

__global__ void __launch_bounds__(256, 3)
layer0_kernel(const float* __restrict__ Wr_i,
              const float* __restrict__ Wls, const float* __restrict__ Wlv,
              const float* __restrict__ Wps, const float* __restrict__ Wpv,
              const float* __restrict__ embed_s,
              const int* __restrict__ species,
              const float* __restrict__ pw_i,
              const float* __restrict__ Wread0,
              float* __restrict__ out)
{
    extern __shared__ float sm[];
    u64* pW1 = (u64*)sm;
    u64* pW2 = (u64*)(sm + 4096);
    u64* pW3 = (u64*)(sm + 8192);
    u64* pW4 = (u64*)(sm + 12288);
    float* sWr = sm + 16384;               // 1024 floats (paths 0,2)
    float* sStageBase = sm + 17408;

    for (int i = threadIdx.x; i < 2048; i += 256) {
        int f2 = i >> 6, g = i & 63;
        int r0 = (2 * f2) * 64 + g, r1 = r0 + 64;
        pW1[i] = pack2(Wls[r0], Wls[r1]);
        pW2[i] = pack2(Wlv[r0], Wlv[r1]);
        pW3[i] = pack2(Wps[r0], Wps[r1]);
        pW4[i] = pack2(Wpv[r0], Wpv[r1]);
    }
    for (int i = threadIdx.x; i < 2 * NBB * 64; i += 256) {
        int p = i >> 9, b = (i >> 6) & 7, f = i & 63;
        sWr[i] = Wr_i[b * 320 + (p ? 128 : 0) + f];
    }
    __syncthreads();

    int wid = threadIdx.x >> 5;
    int t   = threadIdx.x & 31;
    int go  = 2 * t;

    float* stA = sStageBase + wid * 256;   // 64: agg_s / ps
    float* stV = stA + 64;                 // 192: agg_v / pv

#pragma unroll 1
    for (int chunk = 0; chunk < 8; chunk++) {
        int n = blockIdx.x * 64 + chunk * 8 + wid;

        u64 wr0[NBB], wr2[NBB];
#pragma unroll
        for (int b = 0; b < NBB; b++) {
            wr0[b] = *(const u64*)&sWr[b * 64 + go];
            wr2[b] = *(const u64*)&sWr[512 + b * 64 + go];
        }

        int beg = g_off[n], end = g_off[n + 1];
        u64 as = 0ull, ax = 0ull, ay = 0ull, az = 0ull;
#pragma unroll 4
        for (int i = beg; i < end; i++) {
            int sv_ = g_snds[i];
            float4 yv  = g_Y4s[i];
            float4 rba = g_rbf4s[i * 2 + 0];
            float4 rbb = g_rbf4s[i * 2 + 1];
            float rbv[NBB] = {rba.x, rba.y, rba.z, rba.w, rbb.x, rbb.y, rbb.z, rbb.w};

            u64 w0 = 0ull, w2 = 0ull;
#pragma unroll
            for (int b = 0; b < NBB; b++) {
                u64 rb2 = bcast2(rbv[b]);
                w0 = fma2(rb2, wr0[b], w0);
                w2 = fma2(rb2, wr2[b], w2);
            }
            int spec = sv_ >> 20;
            u64 ss = *(const u64*)&embed_s[spec * FF + go];
            as = fma2(w0, ss, as);
            u64 w2s = mul2(w2, ss);
            ax = fma2(w2s, bcast2(yv.x), ax);
            ay = fma2(w2s, bcast2(yv.y), ay);
            az = fma2(w2s, bcast2(yv.z), az);
        }

        {
            float2 fs = u2f(as), fx = u2f(ax), fy = u2f(ay), fz = u2f(az);
            *(float2*)&stA[go]       = make_float2(fs.x * EPS_SC, fs.y * EPS_SC);
            *(float2*)&stV[go]       = make_float2(fx.x * EPS_SC, fx.y * EPS_SC);
            *(float2*)&stV[64 + go]  = make_float2(fy.x * EPS_SC, fy.y * EPS_SC);
            *(float2*)&stV[128 + go] = make_float2(fz.x * EPS_SC, fz.y * EPS_SC);
        }
        __syncwarp();

        u64 aS0 = 0ull, aS1 = 0ull, aX0 = 0ull, aX1 = 0ull;
        u64 aY0 = 0ull, aY1 = 0ull, aZ0 = 0ull, aZ1 = 0ull;
#pragma unroll 4
        for (int f2 = 0; f2 < 32; f2++) {
            u64 vA = *(const u64*)&stA[2 * f2];
            u64 vX = *(const u64*)&stV[2 * f2];
            u64 vY = *(const u64*)&stV[64 + 2 * f2];
            u64 vZ = *(const u64*)&stV[128 + 2 * f2];
            ulonglong2 wls = *(const ulonglong2*)&pW1[f2 * 64 + go];
            ulonglong2 wlv = *(const ulonglong2*)&pW2[f2 * 64 + go];
            aS0 = fma2(vA, wls.x, aS0);  aS1 = fma2(vA, wls.y, aS1);
            aX0 = fma2(vX, wlv.x, aX0);  aX1 = fma2(vX, wlv.y, aX1);
            aY0 = fma2(vY, wlv.x, aY0);  aY1 = fma2(vY, wlv.y, aY1);
            aZ0 = fma2(vZ, wlv.x, aZ0);  aZ1 = fma2(vZ, wlv.y, aZ1);
        }

        float svv[2] = {hsum2(aS0), hsum2(aS1)};
        float vvx[2] = {hsum2(aX0), hsum2(aX1)};
        float vvy[2] = {hsum2(aY0), hsum2(aY1)};
        float vvz[2] = {hsum2(aZ0), hsum2(aZ1)};

        float q[9][2];
        {
            const float* pbp = pw_i + species[n] * 9 * FF + go;
#pragma unroll
            for (int r = 0; r < 9; r++) {
                float2 tmp = *(const float2*)&pbp[r * 64];
                q[r][0] = tmp.x; q[r][1] = tmp.y;
            }
        }
        float ps[2], pc[2];
#pragma unroll
        for (int k = 0; k < 2; k++) {
            float vv = vvx[k]*vvx[k] + vvy[k]*vvy[k] + vvz[k]*vvz[k];
            float sq = svv[k]*svv[k];
            ps[k] = q[0][k]*svv[k] + q[1][k]*sq + q[2][k]*vv + q[3][k]*sq*svv[k] + q[4][k]*svv[k]*vv;
            pc[k] = q[5][k] + q[6][k]*svv[k] + q[7][k]*sq + q[8][k]*vv;
        }

        __syncwarp();
        *(float2*)&stA[go]       = make_float2(ps[0], ps[1]);
        *(float2*)&stV[go]       = make_float2(pc[0]*vvx[0], pc[1]*vvx[1]);
        *(float2*)&stV[64 + go]  = make_float2(pc[0]*vvy[0], pc[1]*vvy[1]);
        *(float2*)&stV[128 + go] = make_float2(pc[0]*vvz[0], pc[1]*vvz[1]);
        __syncwarp();

        u64 tS0 = 0ull, tS1 = 0ull;
        u64 tX0 = 0ull, tX1 = 0ull, tY0 = 0ull, tY1 = 0ull, tZ0 = 0ull, tZ1 = 0ull;
#pragma unroll 4
        for (int f2 = 0; f2 < 32; f2++) {
            u64 vA = *(const u64*)&stA[2 * f2];
            u64 vX = *(const u64*)&stV[2 * f2];
            u64 vY = *(const u64*)&stV[64 + 2 * f2];
            u64 vZ = *(const u64*)&stV[128 + 2 * f2];
            ulonglong2 wps = *(const ulonglong2*)&pW3[f2 * 64 + go];
            ulonglong2 wpv = *(const ulonglong2*)&pW4[f2 * 64 + go];
            tS0 = fma2(vA, wps.x, tS0);  tS1 = fma2(vA, wps.y, tS1);
            tX0 = fma2(vX, wpv.x, tX0);  tX1 = fma2(vX, wpv.y, tX1);
            tY0 = fma2(vY, wpv.x, tY0);  tY1 = fma2(vY, wpv.y, tY1);
            tZ0 = fma2(vZ, wpv.x, tZ0);  tZ1 = fma2(vZ, wpv.y, tZ1);
        }

        float sn0 = hsum2(tS0), sn1 = hsum2(tS1);
        // combined 32B record feeds layer 1
        float* rec = g_sv + ((size_t)n * 32 + t) * 8;
        *(float4*)rec       = make_float4(sn0, sn1, hsum2(tX0), hsum2(tX1));
        *(float4*)(rec + 4) = make_float4(hsum2(tY0), hsum2(tY1),
                                          hsum2(tZ0), hsum2(tZ1));

        float2 wr = *(const float2*)&Wread0[go];
        float tt = sn0 * wr.x + sn1 * wr.y;
#pragma unroll
        for (int o = 16; o > 0; o >>= 1)
            tt += __shfl_xor_sync(0xffffffffu, tt, o);
        if (t == 0) out[n * LL + 0] = tt;
        __syncwarp();
    }
}

// ---------------- layer 1 kernel: 2 warps per node ------------------------------
// Each slot (2 warps) owns a node; warps split the CSR segment (stride 2) and
// the node-phase outputs (o = h*32 + t). Partials combine via shared stage.
#define SMEM_L1 ((16384 + 2560 + 4 * 448) * 4)   /* ~82 KB */

__global__ void __launch_bounds__(256, 2)
layer1_kernel(const float* __restrict__ Wr_i,
              const float* __restrict__ Wls, const float* __restrict__ Wlv,
              const float* __restrict__ Wps,
              const float* __restrict__ skip_s,
              const int* __restrict__ species,
              const float* __restrict__ pw_i,
              const float* __restrict__ Wr1a, const float* __restrict__ Wr1b,
              float* __restrict__ out)
{
    int n0 = g_norder[blockIdx.x * 64];
    if (n0 < 0) return;
    int spec_blk = species[n0];

    extern __shared__ float sm[];
    u64* pW1 = (u64*)sm;
    u64* pW2 = (u64*)(sm + 4096);
    u64* pW3 = (u64*)(sm + 8192);
    u64* pW4 = (u64*)(sm + 12288);          // skip_s packed
    float* sWr = sm + 16384;                // 2560
    float* sStageBase = sm + 18944;         // 4 slots x 448

    {
        const float* ks = skip_s + spec_blk * 4096;
        for (int i = threadIdx.x; i < 2048; i += 256) {
            int f2 = i >> 6, g = i & 63;
            int r0 = (2 * f2) * 64 + g, r1 = r0 + 64;
            pW1[i] = pack2(Wls[r0], Wls[r1]);
            pW2[i] = pack2(Wlv[r0], Wlv[r1]);
            pW3[i] = pack2(Wps[r0], Wps[r1]);
            pW4[i] = pack2(ks[r0], ks[r1]);
        }
        for (int i = threadIdx.x; i < 5 * NBB * 64; i += 256) {
            int p = i >> 9, b = (i >> 6) & 7, f = i & 63;
            sWr[i] = Wr_i[b * 320 + p * 64 + f];
        }
    }
    __syncthreads();

    int wid  = threadIdx.x >> 5;
    int slot = wid >> 1;                   // 0..3
    int h    = wid & 1;                    // warp within pair
    int t    = threadIdx.x & 31;
    int go   = 2 * t;
    int o    = h * 32 + t;                 // node-phase output index
    int bar  = slot + 1;

    float* stA = sStageBase + slot * 448;  // 64:  agg_s / ps / sn
    float* stV = stA + 64;                 // 192: agg_v / pv
    float* stS = stA + 256;                // 64:  old s
    float* stH = stA + 320;                // 64:  readout scratch (uses 16)

    // per-thread product-basis weights for output o
    float P[9];
    {
        const float* pbp = pw_i + spec_blk * 9 * FF + o;
#pragma unroll
        for (int r = 0; r < 9; r++) P[r] = pbp[r * 64];
    }
    float w1a[4];                          // Wr1a column for hidden unit o (<16)
    if (o < HH) {
#pragma unroll
        for (int j = 0; j < 4; j++) {      // loaded lazily in readout instead
            w1a[j] = 0.f;
        }
    }
    (void)w1a;

#pragma unroll 1
    for (int chunk = 0; chunk < 16; chunk++) {
        int n = g_norder[blockIdx.x * 64 + chunk * 4 + slot];
        if (n < 0) continue;               // uniform across the slot's 2 warps

        // ---- radial weights -> registers ----
        u64 wr0[NBB], wr1[NBB], wr2[NBB], wr3[NBB], wr4[NBB];
#pragma unroll
        for (int b = 0; b < NBB; b++) {
            wr0[b] = *(const u64*)&sWr[(0 * 8 + b) * 64 + go];
            wr1[b] = *(const u64*)&sWr[(1 * 8 + b) * 64 + go];
            wr2[b] = *(const u64*)&sWr[(2 * 8 + b) * 64 + go];
            wr3[b] = *(const u64*)&sWr[(3 * 8 + b) * 64 + go];
            wr4[b] = *(const u64*)&sWr[(4 * 8 + b) * 64 + go];
        }

        // ---- edge phase: this warp takes edges beg+h, beg+h+2, ... ----
        int beg = g_off[n], end = g_off[n + 1];
        u64 as = 0ull, ax = 0ull, ay = 0ull, az = 0ull;
#pragma unroll 2
        for (int i = beg + h; i < end; i += 2) {
            int snd = g_snds[i] & 0xFFFFF;
            float4 yv  = g_Y4s[i];
            float4 rba = g_rbf4s[i * 2 + 0];
            float4 rbb = g_rbf4s[i * 2 + 1];
            const float* rec = g_sv + ((size_t)snd * 32 + t) * 8;
            ulonglong2 r0 = *(const ulonglong2*)rec;        // (s, vx)
            ulonglong2 r1 = *(const ulonglong2*)(rec + 4);  // (vy, vz)

            float rbv[NBB] = {rba.x, rba.y, rba.z, rba.w, rbb.x, rbb.y, rbb.z, rbb.w};
            u64 w0 = 0ull, w1 = 0ull, w2 = 0ull, w3 = 0ull, w4 = 0ull;
#pragma unroll
            for (int b = 0; b < NBB; b++) {
                u64 rb2 = bcast2(rbv[b]);
                w0 = fma2(rb2, wr0[b], w0);
                w1 = fma2(rb2, wr1[b], w1);
                w2 = fma2(rb2, wr2[b], w2);
                w3 = fma2(rb2, wr3[b], w3);
                w4 = fma2(rb2, wr4[b], w4);
            }

            u64 ss = r0.x, vx = r0.y, vy = r1.x, vz = r1.y;
            u64 y02 = bcast2(yv.x), y12 = bcast2(yv.y), y22 = bcast2(yv.z);
            u64 dot = fma2(vx, y02, fma2(vy, y12, mul2(vz, y22)));
            as = fma2(w0, ss, fma2(w1, dot, as));
            u64 ny02 = bcast2(-yv.x), ny12 = bcast2(-yv.y), ny22 = bcast2(-yv.z);
            u64 c0 = fma2(vy, y22, mul2(vz, ny12));
            u64 c1 = fma2(vz, y02, mul2(vx, ny22));
            u64 c2 = fma2(vx, y12, mul2(vy, ny02));
            u64 w2s = mul2(w2, ss);
            ax = fma2(w2s, y02, fma2(w3, vx, fma2(w4, c0, ax)));
            ay = fma2(w2s, y12, fma2(w3, vy, fma2(w4, c1, ay)));
            az = fma2(w2s, y22, fma2(w3, vz, fma2(w4, c2, az)));
        }

        // ---- combine 2-warp partials through the stage ----
        if (h == 0) {
            float2 fs = u2f(as), fx = u2f(ax), fy = u2f(ay), fz = u2f(az);
            *(float2*)&stA[go]       = fs;
            *(float2*)&stV[go]       = fx;
            *(float2*)&stV[64 + go]  = fy;
            *(float2*)&stV[128 + go] = fz;
            // node's own s (skip input)
            u64 sOld = *(const u64*)&g_sv[((size_t)n * 32 + t) * 8];
            *(float2*)&stS[go] = u2f(sOld);
        }
        BAR_SLOT(bar);
        if (h == 1) {
            float2 fs = u2f(as), fx = u2f(ax), fy = u2f(ay), fz = u2f(az);
            float2 p;
            p = *(float2*)&stA[go];
            *(float2*)&stA[go] = make_float2((p.x + fs.x) * EPS_SC, (p.y + fs.y) * EPS_SC);
            p = *(float2*)&stV[go];
            *(float2*)&stV[go] = make_float2((p.x + fx.x) * EPS_SC, (p.y + fx.y) * EPS_SC);
            p = *(float2*)&stV[64 + go];
            *(float2*)&stV[64 + go] = make_float2((p.x + fy.x) * EPS_SC, (p.y + fy.y) * EPS_SC);
            p = *(float2*)&stV[128 + go];
            *(float2*)&stV[128 + go] = make_float2((p.x + fz.x) * EPS_SC, (p.y + fz.y) * EPS_SC);
        }
        BAR_SLOT(bar);

        // ---- matvec 1: 64 threads, one output each (f-packed accums) ----
        u64 aS = 0ull, aX = 0ull, aY = 0ull, aZ = 0ull, aK = 0ull;
#pragma unroll 4
        for (int f2 = 0; f2 < 32; f2++) {
            u64 vA  = *(const u64*)&stA[2 * f2];
            u64 vX  = *(const u64*)&stV[2 * f2];
            u64 vY  = *(const u64*)&stV[64 + 2 * f2];
            u64 vZ  = *(const u64*)&stV[128 + 2 * f2];
            u64 vSi = *(const u64*)&stS[2 * f2];
            u64 wls = pW1[f2 * 64 + o];
            u64 wlv = pW2[f2 * 64 + o];
            u64 wks = pW4[f2 * 64 + o];
            aS = fma2(vA,  wls, aS);
            aX = fma2(vX,  wlv, aX);
            aY = fma2(vY,  wlv, aY);
            aZ = fma2(vZ,  wlv, aZ);
            aK = fma2(vSi, wks, aK);
        }
        float sv = hsum2(aS);
        float vx = hsum2(aX), vy = hsum2(aY), vz = hsum2(aZ);
        float sk = hsum2(aK);

        float vv = vx * vx + vy * vy + vz * vz;
        float sq = sv * sv;
        float ps = P[0]*sv + P[1]*sq + P[2]*vv + P[3]*sq*sv + P[4]*sv*vv;

        BAR_SLOT(bar);                     // all reads of stage done
        stA[o] = ps;
        BAR_SLOT(bar);

        // ---- matvec 2: s channel only ----
        u64 tS = 0ull;
#pragma unroll 4
        for (int f2 = 0; f2 < 32; f2++)
            tS = fma2(*(const u64*)&stA[2 * f2], pW3[f2 * 64 + o], tS);
        float sn = hsum2(tS) + sk;

        BAR_SLOT(bar);                     // done reading ps
        stA[o] = sn;
        BAR_SLOT(bar);

        // ---- nonlinear readout: hidden unit o (<16) over staged sn ----
        if (o < HH) {
            float hh = 0.f;
#pragma unroll
            for (int f4 = 0; f4 < FF; f4 += 4) {
                float aa[4];
                *(float4*)aa = *(const float4*)&stA[f4];
#pragma unroll
                for (int j = 0; j < 4; j++)
                    hh = fmaf(aa[j], Wr1a[(f4 + j) * HH + o], hh);
            }
            hh = hh / (1.0f + expf(-hh));  // silu
            stH[o] = hh * Wr1b[o];
        }
        BAR_SLOT(bar);
        if (o == 0) {
            float tt = 0.f;
#pragma unroll
            for (int j = 0; j < HH; j++) tt += stH[j];
            out[n * LL + 1] = tt;
        }
        BAR_SLOT(bar);
    }
}

// ---------------- host launch -------------------------------------------------
extern "C" void kernel_launch(void* const* d_in, const int* in_sizes, int n_in,
                              void* d_out, int out_size)
{
    const float* vectors  = (const float*)d_in[0];
    const float* embed_s  = (const float*)d_in[1];
    const float* Wr       = (const float*)d_in[2];   // [2,8,320]
    const float* Wls      = (const float*)d_in[3];   // [2,64,64]
    const float* Wlv      = (const float*)d_in[4];
    const float* skip_s   = (const float*)d_in[5];   // [10,64,64]
    const float* skip_v   = (const float*)d_in[6];   // dead
    const float* pw       = (const float*)d_in[7];   // [2,10,9,64]
    const float* Wps      = (const float*)d_in[8];
    const float* Wpv      = (const float*)d_in[9];
    const float* Wread0   = (const float*)d_in[10];  // [64,1]
    const float* Wr1a     = (const float*)d_in[11];  // [64,16]
    const float* Wr1b     = (const float*)d_in[12];  // [16,1]
    const int*   senders  = (const int*)d_in[13];
    const int*   receivers= (const int*)d_in[14];
    const int*   species  = (const int*)d_in[15];
    float* out = (float*)d_out;
    (void)skip_v;

    static bool attr_done = false;
    if (!attr_done) {
        cudaFuncSetAttribute((const void*)layer0_kernel,
                             cudaFuncAttributeMaxDynamicSharedMemorySize, SMEM_L0);
        cudaFuncSetAttribute((const void*)layer1_kernel,
                             cudaFuncAttributeMaxDynamicSharedMemorySize, SMEM_L1);
        attr_done = true;
    }

    // ---- preprocessing: 4 launches ----
    zero_sort_kernel<<<(NPAD + 255) / 256, 256>>>();
    hist_kernel<<<EE / 256, 256>>>(receivers, species);
    scan_kernel<<<1, 1024>>>();
    fused_pre_kernel<<<EE / 256, 256>>>(vectors, senders, receivers, species);

    // ---- layer 0 ----
    layer0_kernel<<<NN / 64, 256, SMEM_L0>>>(
        Wr, Wls, Wlv, Wps, Wpv, embed_s, species, pw, Wread0, out);

    // ---- layer 1 (species-grouped; 2 warps/node) ----
    layer1_kernel<<<NPAD / 64, 256, SMEM_L1>>>(
        Wr + NBB * 5 * FF, Wls + FF * FF, Wlv + FF * FF, Wps + FF * FF,
        skip_s, species, pw + ZZ * 9 * FF, Wr1a, Wr1b, out);
}

// round 15
// speedup vs baseline: 1.7792x; 1.7792x over previous
#include <cuda_runtime.h>
#include <cuda_bf16.h>
#include <math.h>

#define NN 32768
#define EE 262144
#define FF 64
#define ZZ 10
#define NBB 8
#define LL 2
#define HH 16
#define NPAD (NN + 64 * ZZ)              /* species-padded node ordering */
#define EPS_SC 0.24253562503633297f      /* 1/sqrt(17) */

typedef unsigned long long u64;

// ---------------- packed fp32x2 helpers ----------------------------------------
__device__ __forceinline__ u64 pack2(float lo, float hi) {
    u64 r; asm("mov.b64 %0, {%1, %2};" : "=l"(r) : "f"(lo), "f"(hi)); return r;
}
__device__ __forceinline__ u64 bcast2(float v) { return pack2(v, v); }
__device__ __forceinline__ float2 u2f(u64 v) {
    float2 r; asm("mov.b64 {%0, %1}, %2;" : "=f"(r.x), "=f"(r.y) : "l"(v)); return r;
}
__device__ __forceinline__ u64 fma2(u64 a, u64 b, u64 c) {
    u64 r; asm("fma.rn.f32x2 %0, %1, %2, %3;" : "=l"(r) : "l"(a), "l"(b), "l"(c)); return r;
}
__device__ __forceinline__ u64 mul2(u64 a, u64 b) {
    u64 r; asm("mul.rn.f32x2 %0, %1, %2;" : "=l"(r) : "l"(a), "l"(b)); return r;
}
__device__ __forceinline__ float hsum2(u64 v) {
    float2 f = u2f(v); return f.x + f.y;
}

// ---------------- scratch (static device globals; no allocation) -------------
// Combined node state: per (node, f-pair t) one 32B record
//   (s[2t], s[2t+1], vx[2t], vx[2t+1], vy[2t], vy[2t+1], vz[2t], vz[2t+1])
__device__ float  g_sv[(size_t)NN * 32 * 8];
__device__ float4 g_rbf4s[EE * 2];       // bessel basis, receiver-sorted
__device__ float4 g_Y4s[EE];             // unit vector, receiver-sorted
__device__ int    g_snds[EE];            // sender | (sender_species << 20), sorted
__device__ int    g_cnt[NN];             // receiver histogram
__device__ int    g_cur[NN];             // scatter cursors
__device__ int    g_off[NN + 1];         // CSR offsets
__device__ int    g_scnt[ZZ];            // species histogram
__device__ int    g_scur[ZZ];
__device__ int    g_norder[NPAD];        // species-grouped node order (-1 pad)

// ---------------- preprocessing ------------------------------------------------
__global__ void zero_sort_kernel()
{
    int i = blockIdx.x * blockDim.x + threadIdx.x;
    if (i < NN)   g_cnt[i] = 0;
    if (i < ZZ)   g_scnt[i] = 0;
    if (i < NPAD) g_norder[i] = -1;
}

__global__ void hist_kernel(const int* __restrict__ receivers,
                            const int* __restrict__ species)
{
    int i = blockIdx.x * blockDim.x + threadIdx.x;
    if (i < EE) atomicAdd(&g_cnt[receivers[i]], 1);
    if (i < NN) atomicAdd(&g_scnt[species[i]], 1);
}

__global__ void scan_kernel()   // 1 block, 1024 threads; NN = 1024*32
{
    __shared__ int part[1024];
    int tid = threadIdx.x;

    if (tid == 0) {             // tiny species scan folded in
        int off = 0;
#pragma unroll
        for (int z = 0; z < ZZ; z++) {
            g_scur[z] = off;
            off += ((g_scnt[z] + 63) / 64) * 64;
        }
    }

    int base = tid * 32;
    int cnt[32];
#pragma unroll
    for (int j = 0; j < 8; j++)
        *(int4*)&cnt[j * 4] = *(const int4*)&g_cnt[base + j * 4];

    int loc[32];
    int sum = 0;
#pragma unroll
    for (int j = 0; j < 32; j++) { loc[j] = sum; sum += cnt[j]; }
    part[tid] = sum;
    __syncthreads();
    for (int o = 1; o < 1024; o <<= 1) {
        int v = (tid >= o) ? part[tid - o] : 0;
        __syncthreads();
        part[tid] += v;
        __syncthreads();
    }
    int pref = part[tid] - sum;
#pragma unroll
    for (int j = 0; j < 32; j++) {
        int o = pref + loc[j];
        g_off[base + j] = o;
        g_cur[base + j] = o;
    }
    if (tid == 1023) g_off[NN] = part[1023];
}

// precompute (edge scatter) + species scatter, one launch
__global__ void fused_pre_kernel(const float* __restrict__ vectors,
                                 const int* __restrict__ senders,
                                 const int* __restrict__ receivers,
                                 const int* __restrict__ species)
{
    int idx = blockIdx.x * blockDim.x + threadIdx.x;   // EE threads

    if (idx < EE) {
        float x = vectors[idx * 3 + 0];
        float y = vectors[idx * 3 + 1];
        float z = vectors[idx * 3 + 2];
        float r2 = x * x + y * y + z * z + 1e-12f;
        float r  = sqrtf(r2);
        float inv = 1.0f / r;
        float rc = fmaxf(r, 1e-6f);
        float r6 = r2 * r2 * r2;
        float env = 1.0f - 28.0f * r6 + 48.0f * r6 * r - 21.0f * r6 * r2;
        if (r >= 1.0f) env = 0.0f;
        float kk = env * 1.4142135623730951f / rc;
        float pr = 3.14159265358979323846f * rc;
        float rb[NBB];
#pragma unroll
        for (int n2 = 1; n2 <= NBB; n2++)
            rb[n2 - 1] = kk * __sinf((float)n2 * pr);

        int snd = senders[idx];
        int pos = atomicAdd(&g_cur[receivers[idx]], 1);
        g_Y4s[pos] = make_float4(x * inv, y * inv, z * inv, 0.f);
        g_rbf4s[pos * 2 + 0] = make_float4(rb[0], rb[1], rb[2], rb[3]);
        g_rbf4s[pos * 2 + 1] = make_float4(rb[4], rb[5], rb[6], rb[7]);
        g_snds[pos] = snd | (species[snd] << 20);
    }

    if (idx < NN) {
        int pos = atomicAdd(&g_scur[species[idx]], 1);
        g_norder[pos] = idx;
    }
}

// ---------------- fused per-layer kernel ---------------------------------------
// One warp per node: CSR edge reduce (f32x2, f-pairs) -> shared stage ->
// f-packed matvecs + product basis + skip + readout.
//
// Shared (floats):
//   [0,4096)      pW1: Wls  packed-over-f (u64[2048])
//   [4096,8192)   pW2: Wlv  packed
//   [8192,12288)  pW3: Wps  packed
//   [12288,16384) pW4: ITER0 Wpv / ITER1 skip_s  packed
//   then sWr: radial weights (L0: 1024 floats, paths 0/2; L1: 2560 floats)
//   then stage: 8 warps x STG
#define SMEM_L0 ((16384 + 1024 + 8 * 256) * 4)   /* 76 KB  */
#define SMEM_L1 ((16384 + 2560 + 8 * 320) * 4)   /* 84 KB  */

template <int ITER>
__global__ void __launch_bounds__(256, ITER == 0 ? 3 : 2)
layer_kernel(const float* __restrict__ Wr_i,     // [8,320] this layer
             const float* __restrict__ Wls, const float* __restrict__ Wlv,
             const float* __restrict__ Wps,
             const float* __restrict__ Wpv,      // ITER0 only
             const float* __restrict__ skip_s,   // ITER1 only
             const float* __restrict__ embed_s,  // ITER0 only [Z,F]
             const int* __restrict__ species,
             const float* __restrict__ pw_i,     // [Z,9,F] this layer
             const float* __restrict__ Wread0,   // ITER0 only
             const float* __restrict__ Wr1a, const float* __restrict__ Wr1b,
             float* __restrict__ out)
{
    int spec_blk = 0;
    if (ITER == 1) {
        int n0 = g_norder[blockIdx.x * 64];
        if (n0 < 0) return;                 // fully-padded block
        spec_blk = species[n0];             // uniform for the whole block
    }

    extern __shared__ float sm[];
    u64* pW1 = (u64*)sm;
    u64* pW2 = (u64*)(sm + 4096);
    u64* pW3 = (u64*)(sm + 8192);
    u64* pW4 = (u64*)(sm + 12288);
    float* sWr = sm + 16384;
    float* sStageBase = (ITER == 0) ? (sm + 16384 + 1024) : (sm + 16384 + 2560);
    const int STG = (ITER == 0) ? 256 : 320;

    // ---- repack weights over f-pairs: pW[f2*64+g] = (W[2f2][g], W[2f2+1][g]) ----
    {
        const float* W4src = (ITER == 0) ? Wpv : (skip_s + spec_blk * 4096);
        for (int i = threadIdx.x; i < 2048; i += 256) {
            int f2 = i >> 6, g = i & 63;
            int r0 = (2 * f2) * 64 + g, r1 = r0 + 64;
            pW1[i] = pack2(Wls[r0], Wls[r1]);
            pW2[i] = pack2(Wlv[r0], Wlv[r1]);
            pW3[i] = pack2(Wps[r0], Wps[r1]);
            pW4[i] = pack2(W4src[r0], W4src[r1]);
        }
    }
    if (ITER == 0) {
        // only radial paths 0 and 2 exist in layer 0
        for (int i = threadIdx.x; i < 2 * NBB * 64; i += 256) {
            int p = i >> 9, b = (i >> 6) & 7, f = i & 63;
            sWr[i] = Wr_i[b * 320 + (p ? 128 : 0) + f];
        }
    } else {
        for (int i = threadIdx.x; i < 5 * NBB * 64; i += 256) {
            int p = i >> 9, b = (i >> 6) & 7, f = i & 63;
            sWr[i] = Wr_i[b * 320 + p * 64 + f];
        }
    }
    __syncthreads();

    int wid  = threadIdx.x >> 5;
    int t    = threadIdx.x & 31;       // f-pair (edge phase) / lane
    int go   = 2 * t;                  // output pair (node phase)

    float* stA  = sStageBase + wid * STG;  // 64:  agg_s / ps / staged sn
    float* stV  = stA + 64;                // 192: agg_v / pv
    float* stS  = stA + 256;               // 64:  old s (ITER1)

    // per-block product-basis weights (ITER1: species uniform)
    float P1[9][2];
    if (ITER == 1) {
        const float* pbp = pw_i + spec_blk * 9 * FF + go;
#pragma unroll
        for (int r = 0; r < 9; r++) {
            float2 tmp = *(const float2*)&pbp[r * 64];
            P1[r][0] = tmp.x; P1[r][1] = tmp.y;
        }
    }

#pragma unroll 1
    for (int chunk = 0; chunk < 8; chunk++) {
        int n;
        if (ITER == 0) {
            n = blockIdx.x * 64 + chunk * 8 + wid;
        } else {
            n = g_norder[blockIdx.x * 64 + chunk * 8 + wid];
            if (n < 0) continue;           // warp-uniform
        }

        // ---- radial weights -> registers (live only through edge phase) ----
        u64 wr0[NBB], wr1[NBB], wr2[NBB], wr3[NBB], wr4[NBB];
#pragma unroll
        for (int b = 0; b < NBB; b++) {
            if (ITER == 0) {
                wr0[b] = *(const u64*)&sWr[b * 64 + go];
                wr2[b] = *(const u64*)&sWr[512 + b * 64 + go];
            } else {
                wr0[b] = *(const u64*)&sWr[(0 * 8 + b) * 64 + go];
                wr1[b] = *(const u64*)&sWr[(1 * 8 + b) * 64 + go];
                wr2[b] = *(const u64*)&sWr[(2 * 8 + b) * 64 + go];
                wr3[b] = *(const u64*)&sWr[(3 * 8 + b) * 64 + go];
                wr4[b] = *(const u64*)&sWr[(4 * 8 + b) * 64 + go];
            }
        }

        // ---- edge phase: walk CSR segment, accumulate in regs ----
        int beg = g_off[n], end = g_off[n + 1];
        u64 as = 0ull, ax = 0ull, ay = 0ull, az = 0ull;

        if (ITER == 0) {
#pragma unroll 4
            for (int i = beg; i < end; i++) {
                int sv_ = g_snds[i];
                int spec = sv_ >> 20;                // sender species
                float4 yv  = g_Y4s[i];
                float4 rba = g_rbf4s[i * 2 + 0];
                float4 rbb = g_rbf4s[i * 2 + 1];
                float rb[NBB] = {rba.x, rba.y, rba.z, rba.w, rbb.x, rbb.y, rbb.z, rbb.w};

                u64 w0 = 0ull, w2 = 0ull;
#pragma unroll
                for (int b = 0; b < NBB; b++) {
                    u64 rb2 = bcast2(rb[b]);
                    w0 = fma2(rb2, wr0[b], w0);
                    w2 = fma2(rb2, wr2[b], w2);
                }

                // s0[snd] == embed_s[species[snd]] — 10 hot rows, no big gather
                u64 ss = *(const u64*)&embed_s[spec * FF + go];
                as = fma2(w0, ss, as);
                u64 w2s = mul2(w2, ss);
                ax = fma2(w2s, bcast2(yv.x), ax);
                ay = fma2(w2s, bcast2(yv.y), ay);
                az = fma2(w2s, bcast2(yv.z), az);
            }
        } else {
#pragma unroll 2
            for (int i = beg; i < end; i++) {
                int snd = g_snds[i] & 0xFFFFF;
                float4 yv  = g_Y4s[i];
                float4 rba = g_rbf4s[i * 2 + 0];
                float4 rbb = g_rbf4s[i * 2 + 1];
                // fused state record: 2x LDG.128 on one address stream
                const float* rec = g_sv + ((size_t)snd * 32 + t) * 8;
                ulonglong2 r0 = *(const ulonglong2*)rec;        // (s, vx)
                ulonglong2 r1 = *(const ulonglong2*)(rec + 4);  // (vy, vz)

                float rb[NBB] = {rba.x, rba.y, rba.z, rba.w, rbb.x, rbb.y, rbb.z, rbb.w};
                u64 w0 = 0ull, w1 = 0ull, w2 = 0ull, w3 = 0ull, w4 = 0ull;
#pragma unroll
                for (int b = 0; b < NBB; b++) {
                    u64 rb2 = bcast2(rb[b]);
                    w0 = fma2(rb2, wr0[b], w0);
                    w1 = fma2(rb2, wr1[b], w1);
                    w2 = fma2(rb2, wr2[b], w2);
                    w3 = fma2(rb2, wr3[b], w3);
                    w4 = fma2(rb2, wr4[b], w4);
                }

                u64 ss = r0.x, vx = r0.y, vy = r1.x, vz = r1.y;
                u64 y02 = bcast2(yv.x), y12 = bcast2(yv.y), y22 = bcast2(yv.z);
                u64 dot = fma2(vx, y02, fma2(vy, y12, mul2(vz, y22)));
                as = fma2(w0, ss, fma2(w1, dot, as));
                u64 ny02 = bcast2(-yv.x), ny12 = bcast2(-yv.y), ny22 = bcast2(-yv.z);
                u64 c0 = fma2(vy, y22, mul2(vz, ny12));
                u64 c1 = fma2(vz, y02, mul2(vx, ny22));
                u64 c2 = fma2(vx, y12, mul2(vy, ny02));
                u64 w2s = mul2(w2, ss);
                ax = fma2(w2s, y02, fma2(w3, vx, fma2(w4, c0, ax)));
                ay = fma2(w2s, y12, fma2(w3, vy, fma2(w4, c1, ay)));
                az = fma2(w2s, y22, fma2(w3, vz, fma2(w4, c2, az)));
            }
        }

        // ---- stage edge results (+EPS) and skip input ----
        {
            float2 fs = u2f(as), fx = u2f(ax), fy = u2f(ay), fz = u2f(az);
            *(float2*)&stA[go]       = make_float2(fs.x * EPS_SC, fs.y * EPS_SC);
            *(float2*)&stV[go]       = make_float2(fx.x * EPS_SC, fx.y * EPS_SC);
            *(float2*)&stV[64 + go]  = make_float2(fy.x * EPS_SC, fy.y * EPS_SC);
            *(float2*)&stV[128 + go] = make_float2(fz.x * EPS_SC, fz.y * EPS_SC);
        }
        if (ITER > 0) {
            u64 sOld = *(const u64*)&g_sv[((size_t)n * 32 + t) * 8];  // s half of record
            *(float2*)&stS[go] = u2f(sOld);
        }
        __syncwarp();

        // ---- matvec 1 (f-packed: no broadcasts) ----
        u64 aS0 = 0ull, aS1 = 0ull, aX0 = 0ull, aX1 = 0ull;
        u64 aY0 = 0ull, aY1 = 0ull, aZ0 = 0ull, aZ1 = 0ull;
        u64 aK0 = 0ull, aK1 = 0ull;
#pragma unroll 4
        for (int f2 = 0; f2 < 32; f2++) {
            u64 vA = *(const u64*)&stA[2 * f2];
            u64 vX = *(const u64*)&stV[2 * f2];
            u64 vY = *(const u64*)&stV[64 + 2 * f2];
            u64 vZ = *(const u64*)&stV[128 + 2 * f2];
            ulonglong2 wls = *(const ulonglong2*)&pW1[f2 * 64 + go];
            ulonglong2 wlv = *(const ulonglong2*)&pW2[f2 * 64 + go];
            aS0 = fma2(vA, wls.x, aS0);  aS1 = fma2(vA, wls.y, aS1);
            aX0 = fma2(vX, wlv.x, aX0);  aX1 = fma2(vX, wlv.y, aX1);
            aY0 = fma2(vY, wlv.x, aY0);  aY1 = fma2(vY, wlv.y, aY1);
            aZ0 = fma2(vZ, wlv.x, aZ0);  aZ1 = fma2(vZ, wlv.y, aZ1);
            if (ITER > 0) {
                u64 vSi = *(const u64*)&stS[2 * f2];
                ulonglong2 wks = *(const ulonglong2*)&pW4[f2 * 64 + go];
                aK0 = fma2(vSi, wks.x, aK0);  aK1 = fma2(vSi, wks.y, aK1);
            }
        }

        float svv[2] = {hsum2(aS0), hsum2(aS1)};
        float vvx[2] = {hsum2(aX0), hsum2(aX1)};
        float vvy[2] = {hsum2(aY0), hsum2(aY1)};
        float vvz[2] = {hsum2(aZ0), hsum2(aZ1)};
        float sk[2]  = {hsum2(aK0), hsum2(aK1)};

        // ---- product basis (2 outputs) ----
        float q[9][2];
        if (ITER == 0) {
            const float* pbp = pw_i + species[n] * 9 * FF + go;
#pragma unroll
            for (int r = 0; r < 9; r++) {
                float2 tmp = *(const float2*)&pbp[r * 64];
                q[r][0] = tmp.x; q[r][1] = tmp.y;
            }
        } else {
#pragma unroll
            for (int r = 0; r < 9; r++) { q[r][0] = P1[r][0]; q[r][1] = P1[r][1]; }
        }

        float ps[2], pc[2];
#pragma unroll
        for (int k = 0; k < 2; k++) {
            float vv = vvx[k]*vvx[k] + vvy[k]*vvy[k] + vvz[k]*vvz[k];
            float sq = svv[k]*svv[k];
            ps[k] = q[0][k]*svv[k] + q[1][k]*sq + q[2][k]*vv + q[3][k]*sq*svv[k] + q[4][k]*svv[k]*vv;
            pc[k] = q[5][k] + q[6][k]*svv[k] + q[7][k]*sq + q[8][k]*vv;
        }

        __syncwarp();
        *(float2*)&stA[go] = make_float2(ps[0], ps[1]);
        if (ITER == 0) {
            *(float2*)&stV[go]       = make_float2(pc[0]*vvx[0], pc[1]*vvx[1]);
            *(float2*)&stV[64 + go]  = make_float2(pc[0]*vvy[0], pc[1]*vvy[1]);
            *(float2*)&stV[128 + go] = make_float2(pc[0]*vvz[0], pc[1]*vvz[1]);
        }
        __syncwarp();

        // ---- matvec 2 (f-packed) ----
        u64 tS0 = 0ull, tS1 = 0ull;
        u64 tX0 = 0ull, tX1 = 0ull, tY0 = 0ull, tY1 = 0ull, tZ0 = 0ull, tZ1 = 0ull;
#pragma unroll 4
        for (int f2 = 0; f2 < 32; f2++) {
            u64 vA = *(const u64*)&stA[2 * f2];
            ulonglong2 wps = *(const ulonglong2*)&pW3[f2 * 64 + go];
            tS0 = fma2(vA, wps.x, tS0);  tS1 = fma2(vA, wps.y, tS1);
            if (ITER == 0) {
                u64 vX = *(const u64*)&stV[2 * f2];
                u64 vY = *(const u64*)&stV[64 + 2 * f2];
                u64 vZ = *(const u64*)&stV[128 + 2 * f2];
                ulonglong2 wpv = *(const ulonglong2*)&pW4[f2 * 64 + go];
                tX0 = fma2(vX, wpv.x, tX0);  tX1 = fma2(vX, wpv.y, tX1);
                tY0 = fma2(vY, wpv.x, tY0);  tY1 = fma2(vY, wpv.y, tY1);
                tZ0 = fma2(vZ, wpv.x, tZ0);  tZ1 = fma2(vZ, wpv.y, tZ1);
            }
        }

        float sn[2] = {hsum2(tS0), hsum2(tS1)};
        if (ITER > 0) { sn[0] += sk[0]; sn[1] += sk[1]; }

        if (ITER == 0) {
            // outputs feed layer 1: one combined 32B record per (n, f-pair)
            float* rec = g_sv + ((size_t)n * 32 + t) * 8;
            *(float4*)rec       = make_float4(sn[0], sn[1], hsum2(tX0), hsum2(tX1));
            *(float4*)(rec + 4) = make_float4(hsum2(tY0), hsum2(tY1),
                                              hsum2(tZ0), hsum2(tZ1));

            // linear readout
            float2 wr = *(const float2*)&Wread0[go];
            float tt = sn[0] * wr.x + sn[1] * wr.y;
#pragma unroll
            for (int o = 16; o > 0; o >>= 1)
                tt += __shfl_xor_sync(0xffffffffu, tt, o);
            if (t == 0) out[n * LL + 0] = tt;
        } else {
            // nonlinear readout
            __syncwarp();
            *(float2*)&stA[go] = make_float2(sn[0], sn[1]);
            __syncwarp();
            float tt = 0.f;
            if (t < HH) {
                float h = 0.f;
#pragma unroll
                for (int f4 = 0; f4 < FF; f4 += 4) {
                    float aa[4];
                    *(float4*)aa = *(const float4*)&stA[f4];
#pragma unroll
                    for (int j = 0; j < 4; j++)
                        h = fmaf(aa[j], Wr1a[(f4 + j) * HH + t], h);
                }
                h = h / (1.0f + expf(-h));  // silu
                tt = h * Wr1b[t];
            }
#pragma unroll
            for (int o = 16; o > 0; o >>= 1)
                tt += __shfl_xor_sync(0xffffffffu, tt, o);
            if (t == 0) out[n * LL + 1] = tt;
        }
        __syncwarp();
    }
}

// ---------------- host launch -------------------------------------------------
extern "C" void kernel_launch(void* const* d_in, const int* in_sizes, int n_in,
                              void* d_out, int out_size)
{
    const float* vectors  = (const float*)d_in[0];
    const float* embed_s  = (const float*)d_in[1];
    const float* Wr       = (const float*)d_in[2];   // [2,8,320]
    const float* Wls      = (const float*)d_in[3];   // [2,64,64]
    const float* Wlv      = (const float*)d_in[4];
    const float* skip_s   = (const float*)d_in[5];   // [10,64,64]
    const float* skip_v   = (const float*)d_in[6];   // dead: layer-1 v unused
    const float* pw       = (const float*)d_in[7];   // [2,10,9,64]
    const float* Wps      = (const float*)d_in[8];
    const float* Wpv      = (const float*)d_in[9];
    const float* Wread0   = (const float*)d_in[10];  // [64,1]
    const float* Wr1a     = (const float*)d_in[11];  // [64,16]
    const float* Wr1b     = (const float*)d_in[12];  // [16,1]
    const int*   senders  = (const int*)d_in[13];
    const int*   receivers= (const int*)d_in[14];
    const int*   species  = (const int*)d_in[15];
    float* out = (float*)d_out;
    (void)skip_v;

    static bool attr_done = false;
    if (!attr_done) {
        cudaFuncSetAttribute((const void*)layer_kernel<0>,
                             cudaFuncAttributeMaxDynamicSharedMemorySize, SMEM_L0);
        cudaFuncSetAttribute((const void*)layer_kernel<1>,
                             cudaFuncAttributeMaxDynamicSharedMemorySize, SMEM_L1);
        attr_done = true;
    }

    // ---- preprocessing: 4 launches ----
    zero_sort_kernel<<<(NPAD + 255) / 256, 256>>>();
    hist_kernel<<<EE / 256, 256>>>(receivers, species);
    scan_kernel<<<1, 1024>>>();
    fused_pre_kernel<<<EE / 256, 256>>>(vectors, senders, receivers, species);

    // ---- layer 0 (fused edge reduce + node update + linear readout) ----
    layer_kernel<0><<<NN / 64, 256, SMEM_L0>>>(
        Wr, Wls, Wlv, Wps, Wpv, nullptr, embed_s,
        species, pw, Wread0, nullptr, nullptr, out);

    // ---- layer 1 (species-grouped; fused; nonlinear readout) ----
    layer_kernel<1><<<NPAD / 64, 256, SMEM_L1>>>(
        Wr + NBB * 5 * FF, Wls + FF * FF, Wlv + FF * FF, Wps + FF * FF,
        nullptr, skip_s, nullptr,
        species, pw + ZZ * 9 * FF, nullptr, Wr1a, Wr1b, out);
}